// round 3
// baseline (speedup 1.0000x reference)
#include <cuda_runtime.h>
#include <cstdint>

// Problem constants
#define NN 50000
#define EE 500000
// x row = 128 node feats + 3 coords = 131
// e_in = 257 (dst 128, src 128, dist 1), padded to 260

__device__ float g_m[NN * 64];   // segment-sum of m_ij
__device__ float g_w[NN];        // segment-sum of coord_w
__device__ float g_r[NN * 3];    // segment-sum of rel_coords
__device__ int   g_is64;         // edge_index dtype flag (1 = int64, 0 = int32)

__device__ __forceinline__ float silu_f(float v) {
    return __fdividef(v, 1.0f + __expf(-v));
}

// ---------------------------------------------------------------------------
// Detect edge_index dtype: int64 little-endian with values < 2^31 has every
// odd 32-bit word == 0; int32 node ids are random in [0, 50000).
// ---------------------------------------------------------------------------
__global__ void detect_kernel(const int* __restrict__ ei32) {
    if (threadIdx.x == 0 && blockIdx.x == 0) {
        int allzero = 1;
        #pragma unroll 1
        for (int i = 0; i < 64; i++) {
            if (ei32[2 * i + 1] != 0) { allzero = 0; break; }
        }
        g_is64 = allzero;
    }
}

// ---------------------------------------------------------------------------
// Zero accumulators (runs every launch; graph replays need fresh zeros)
// ---------------------------------------------------------------------------
__global__ void zero_kernel() {
    int stride = gridDim.x * blockDim.x;
    int i = blockIdx.x * blockDim.x + threadIdx.x;
    for (int k = i; k < NN * 64; k += stride) g_m[k] = 0.0f;
    for (int k = i; k < NN; k += stride) g_w[k] = 0.0f;
    for (int k = i; k < NN * 3; k += stride) g_r[k] = 0.0f;
}

// ---------------------------------------------------------------------------
// Fused edge kernel: gather -> GEMM1(257->514)+silu -> GEMM2(514->64)+silu
//                    -> GEMM3(64->256)+silu -> dot W_c2 -> atomics
// 128 edges per block, 256 threads.
// Shared layout (floats):
//   s_ein [128][260]   off 0      (33280)   (reused as s_m [64][132] later)
//   s_w1  [260][32]    off 33280  (8320)    (reused as Wc1 chunk [64][32])
//   s_h   [32][132]    off 41600  (4224)
//   s_w2  [32][64]     off 45824  (2048)
//   s_rel [128][3]     off 47872  (384)
//   s_dst [128] int    off 48256  (128)
// total 48384 floats = 193536 bytes
// ---------------------------------------------------------------------------
#define EDGE_SMEM_BYTES 193536

__global__ __launch_bounds__(256)
void edge_kernel(const float* __restrict__ x,
                 const void* __restrict__ ei_raw,
                 const float* __restrict__ We1, const float* __restrict__ be1,
                 const float* __restrict__ We2, const float* __restrict__ be2,
                 const float* __restrict__ Wc1, const float* __restrict__ bc1,
                 const float* __restrict__ Wc2, const float* __restrict__ bc2)
{
    extern __shared__ float sm[];
    float* s_ein = sm;            // [128][260]
    float* s_w1  = sm + 33280;    // [260][32]
    float* s_h   = sm + 41600;    // [32][132]
    float* s_w2  = sm + 45824;    // [32][64]
    float* s_rel = sm + 47872;    // [128][3]
    int*   s_dst = (int*)(sm + 48256);
    float* s_m   = sm;            // alias of s_ein region: [64][132]

    const int tid  = threadIdx.x;
    const int lane = tid & 31;
    const int wrp  = tid >> 5;
    const int is64 = g_is64;
    const long long* ei64 = (const long long*)ei_raw;
    const int*       ei32 = (const int*)ei_raw;

    // ---------------- gather phase ----------------
    long long ebase = (long long)blockIdx.x * 128;
    for (int e = wrp; e < 128; e += 8) {
        long long ge = ebase + e;
        int s = -1, d = -1;
        if (ge < EE) {
            if (is64) {
                s = (int)ei64[ge];
                d = (int)ei64[EE + ge];
            } else {
                s = ei32[ge];
                d = ei32[EE + ge];
            }
            if (s < 0 || s >= NN || d < 0 || d >= NN) { s = -1; d = -1; }
        }
        if (d >= 0) {
            const float* xs = x + (long long)s * 131;
            const float* xd = x + (long long)d * 131;
            #pragma unroll
            for (int c = lane; c < 128; c += 32) {
                s_ein[e * 260 + c]       = xd[c];
                s_ein[e * 260 + 128 + c] = xs[c];
            }
            float r0 = xs[128] - xd[128];
            float r1 = xs[129] - xd[129];
            float r2 = xs[130] - xd[130];
            float dist = sqrtf(r0 * r0 + r1 * r1 + r2 * r2);
            if (lane == 0) {
                s_ein[e * 260 + 256] = dist;
                s_ein[e * 260 + 257] = 0.0f;
                s_ein[e * 260 + 258] = 0.0f;
                s_ein[e * 260 + 259] = 0.0f;
                s_rel[e * 3 + 0] = r0;
                s_rel[e * 3 + 1] = r1;
                s_rel[e * 3 + 2] = r2;
                s_dst[e] = d;
            }
        } else {
            for (int c = lane; c < 260; c += 32) s_ein[e * 260 + c] = 0.0f;
            if (lane == 0) {
                s_rel[e * 3 + 0] = 0.0f; s_rel[e * 3 + 1] = 0.0f; s_rel[e * 3 + 2] = 0.0f;
                s_dst[e] = -1;
            }
        }
    }
    __syncthreads();

    const int tx = tid & 15;       // 16 col-threads
    const int ty = tid >> 4;       // 16 edge-groups of 8
    const int e0 = ty * 8;

    float macc[8][4];
    #pragma unroll
    for (int i = 0; i < 8; i++)
        #pragma unroll
        for (int j = 0; j < 4; j++) macc[i][j] = 0.0f;

    // ---------------- GEMM1 + GEMM2 fused over 514-dim in 32-col chunks ----
    for (int c0 = 0; c0 < 514; c0 += 32) {
        // load W_e1 chunk [260][32] (zero-padded k>=257, col>=514)
        for (int idx = tid; idx < 8320; idx += 256) {
            int k = idx >> 5, j = idx & 31;
            int col = c0 + j;
            s_w1[idx] = (k < 257 && col < 514) ? We1[k * 514 + col] : 0.0f;
        }
        __syncthreads();

        float acc[8][2];
        #pragma unroll
        for (int i = 0; i < 8; i++) { acc[i][0] = 0.0f; acc[i][1] = 0.0f; }

        for (int k = 0; k < 260; k += 4) {
            float4 a[8];
            #pragma unroll
            for (int i = 0; i < 8; i++)
                a[i] = *(const float4*)&s_ein[(e0 + i) * 260 + k];
            #pragma unroll
            for (int kk = 0; kk < 4; kk++) {
                float2 bv = *(const float2*)&s_w1[(k + kk) * 32 + (tx << 1)];
                #pragma unroll
                for (int i = 0; i < 8; i++) {
                    float av = (kk == 0) ? a[i].x : (kk == 1) ? a[i].y : (kk == 2) ? a[i].z : a[i].w;
                    acc[i][0] = fmaf(av, bv.x, acc[i][0]);
                    acc[i][1] = fmaf(av, bv.y, acc[i][1]);
                }
            }
        }
        __syncthreads();

        // silu + write h chunk (col-major [c][e]); load W_e2 chunk
        float bb0 = (c0 + tx * 2     < 514) ? be1[c0 + tx * 2]     : 0.0f;
        float bb1 = (c0 + tx * 2 + 1 < 514) ? be1[c0 + tx * 2 + 1] : 0.0f;
        #pragma unroll
        for (int i = 0; i < 8; i++) {
            s_h[(tx * 2    ) * 132 + e0 + i] = silu_f(acc[i][0] + bb0);
            s_h[(tx * 2 + 1) * 132 + e0 + i] = silu_f(acc[i][1] + bb1);
        }
        for (int idx = tid; idx < 2048; idx += 256) {
            int k = idx >> 6, j = idx & 63;
            int row = c0 + k;
            s_w2[idx] = (row < 514) ? We2[row * 64 + j] : 0.0f;
        }
        __syncthreads();

        // GEMM2: m += h_chunk @ We2_chunk
        #pragma unroll 4
        for (int c = 0; c < 32; c++) {
            float4 a0 = *(const float4*)&s_h[c * 132 + e0];
            float4 a1 = *(const float4*)&s_h[c * 132 + e0 + 4];
            float4 bv = *(const float4*)&s_w2[c * 64 + (tx << 2)];
            #pragma unroll
            for (int j = 0; j < 4; j++) {
                float bj = (j == 0) ? bv.x : (j == 1) ? bv.y : (j == 2) ? bv.z : bv.w;
                macc[0][j] = fmaf(a0.x, bj, macc[0][j]);
                macc[1][j] = fmaf(a0.y, bj, macc[1][j]);
                macc[2][j] = fmaf(a0.z, bj, macc[2][j]);
                macc[3][j] = fmaf(a0.w, bj, macc[3][j]);
                macc[4][j] = fmaf(a1.x, bj, macc[4][j]);
                macc[5][j] = fmaf(a1.y, bj, macc[5][j]);
                macc[6][j] = fmaf(a1.z, bj, macc[6][j]);
                macc[7][j] = fmaf(a1.w, bj, macc[7][j]);
            }
        }
        __syncthreads();
    }

    // ---------------- m_ij = silu(m + b_e2); store + atomic scatter --------
    float mval[8][4];
    #pragma unroll
    for (int j = 0; j < 4; j++) {
        float b = be2[tx * 4 + j];
        #pragma unroll
        for (int i = 0; i < 8; i++) mval[i][j] = silu_f(macc[i][j] + b);
    }
    // write m to shared (n-major [n][e]) — s_ein no longer needed
    #pragma unroll
    for (int j = 0; j < 4; j++)
        #pragma unroll
        for (int i = 0; i < 8; i++)
            s_m[(tx * 4 + j) * 132 + e0 + i] = mval[i][j];
    // scatter m_i
    #pragma unroll
    for (int i = 0; i < 8; i++) {
        int d = s_dst[e0 + i];
        if (d >= 0) {
            #pragma unroll
            for (int j = 0; j < 4; j++)
                atomicAdd(&g_m[d * 64 + tx * 4 + j], mval[i][j]);
        }
    }
    __syncthreads();

    // ---------------- GEMM3 (64->256) + silu + dot W_c2 --------------------
    float cw[8];
    #pragma unroll
    for (int i = 0; i < 8; i++) cw[i] = 0.0f;

    for (int c0 = 0; c0 < 256; c0 += 32) {
        for (int idx = tid; idx < 2048; idx += 256) {
            int k = idx >> 5, j = idx & 31;
            s_w1[idx] = Wc1[k * 256 + c0 + j];   // reuse s_w1 region [64][32]
        }
        __syncthreads();

        float acc[8][2];
        #pragma unroll
        for (int i = 0; i < 8; i++) { acc[i][0] = 0.0f; acc[i][1] = 0.0f; }

        for (int k = 0; k < 64; k += 4) {
            #pragma unroll
            for (int kk = 0; kk < 4; kk++) {
                float4 a0 = *(const float4*)&s_m[(k + kk) * 132 + e0];
                float4 a1 = *(const float4*)&s_m[(k + kk) * 132 + e0 + 4];
                float2 bv = *(const float2*)&s_w1[(k + kk) * 32 + (tx << 1)];
                acc[0][0] = fmaf(a0.x, bv.x, acc[0][0]); acc[0][1] = fmaf(a0.x, bv.y, acc[0][1]);
                acc[1][0] = fmaf(a0.y, bv.x, acc[1][0]); acc[1][1] = fmaf(a0.y, bv.y, acc[1][1]);
                acc[2][0] = fmaf(a0.z, bv.x, acc[2][0]); acc[2][1] = fmaf(a0.z, bv.y, acc[2][1]);
                acc[3][0] = fmaf(a0.w, bv.x, acc[3][0]); acc[3][1] = fmaf(a0.w, bv.y, acc[3][1]);
                acc[4][0] = fmaf(a1.x, bv.x, acc[4][0]); acc[4][1] = fmaf(a1.x, bv.y, acc[4][1]);
                acc[5][0] = fmaf(a1.y, bv.x, acc[5][0]); acc[5][1] = fmaf(a1.y, bv.y, acc[5][1]);
                acc[6][0] = fmaf(a1.z, bv.x, acc[6][0]); acc[6][1] = fmaf(a1.z, bv.y, acc[6][1]);
                acc[7][0] = fmaf(a1.w, bv.x, acc[7][0]); acc[7][1] = fmaf(a1.w, bv.y, acc[7][1]);
            }
        }
        float bb0 = bc1[c0 + tx * 2], bb1 = bc1[c0 + tx * 2 + 1];
        float w20 = Wc2[c0 + tx * 2], w21 = Wc2[c0 + tx * 2 + 1];
        #pragma unroll
        for (int i = 0; i < 8; i++)
            cw[i] += silu_f(acc[i][0] + bb0) * w20 + silu_f(acc[i][1] + bb1) * w21;
        __syncthreads();
    }

    // reduce coord_w over the 16 tx lanes (same half-warp)
    #pragma unroll
    for (int off = 8; off >= 1; off >>= 1)
        #pragma unroll
        for (int i = 0; i < 8; i++)
            cw[i] += __shfl_xor_sync(0xffffffffu, cw[i], off);

    if (tx == 0) {
        float bc2v = bc2[0];
        #pragma unroll
        for (int i = 0; i < 8; i++) {
            int d = s_dst[e0 + i];
            if (d >= 0) {
                atomicAdd(&g_w[d], cw[i] + bc2v);
                atomicAdd(&g_r[d * 3 + 0], s_rel[(e0 + i) * 3 + 0]);
                atomicAdd(&g_r[d * 3 + 1], s_rel[(e0 + i) * 3 + 1]);
                atomicAdd(&g_r[d * 3 + 2], s_rel[(e0 + i) * 3 + 2]);
            }
        }
    }
}

// ---------------------------------------------------------------------------
// Node kernel: coords_out + fused MLP (192->256 silu ->128) + residual
// 64 nodes per block, 256 threads.
// ---------------------------------------------------------------------------
#define NODE_SMEM_BYTES 149504

__global__ __launch_bounds__(256)
void node_kernel(const float* __restrict__ x,
                 const float* __restrict__ Wn1, const float* __restrict__ bn1,
                 const float* __restrict__ Wn2, const float* __restrict__ bn2,
                 float* __restrict__ out)
{
    extern __shared__ float sm[];
    float* s_nin = sm;              // [64][196]
    float* s_w1  = sm + 12544;      // [192][64]
    float* s_h1  = sm + 24832;      // [64][68]
    float* s_w2  = sm + 29184;      // [64][128]

    const int tid  = threadIdx.x;
    const int lane = tid & 31;
    const int wrp  = tid >> 5;
    const int b0   = blockIdx.x * 64;

    for (int i = wrp; i < 64; i += 8) {
        int g = b0 + i;
        if (g < NN) {
            const float* xr = x + (long long)g * 131;
            #pragma unroll
            for (int c = lane; c < 128; c += 32) s_nin[i * 196 + c] = xr[c];
            #pragma unroll
            for (int c = lane; c < 64; c += 32) s_nin[i * 196 + 128 + c] = g_m[g * 64 + c];
            if (lane < 4) s_nin[i * 196 + 192 + lane] = 0.0f;
            if (lane < 3)
                out[(long long)g * 131 + 128 + lane] = xr[128 + lane] + g_w[g] * g_r[g * 3 + lane];
        } else {
            for (int c = lane; c < 196; c += 32) s_nin[i * 196 + c] = 0.0f;
        }
    }
    __syncthreads();

    const int tx = tid & 15;
    const int ty = tid >> 4;

    float acc2[4][8];
    #pragma unroll
    for (int i = 0; i < 4; i++)
        #pragma unroll
        for (int j = 0; j < 8; j++) acc2[i][j] = 0.0f;

    for (int c0 = 0; c0 < 256; c0 += 64) {
        for (int idx = tid; idx < 12288; idx += 256) {
            int k = idx >> 6, j = idx & 63;
            s_w1[idx] = Wn1[k * 256 + c0 + j];
        }
        __syncthreads();

        float acc1[4][4];
        #pragma unroll
        for (int i = 0; i < 4; i++)
            #pragma unroll
            for (int j = 0; j < 4; j++) acc1[i][j] = 0.0f;

        for (int k = 0; k < 192; k += 4) {
            float4 a[4];
            #pragma unroll
            for (int i = 0; i < 4; i++)
                a[i] = *(const float4*)&s_nin[(ty * 4 + i) * 196 + k];
            #pragma unroll
            for (int kk = 0; kk < 4; kk++) {
                float4 bv = *(const float4*)&s_w1[(k + kk) * 64 + (tx << 2)];
                #pragma unroll
                for (int i = 0; i < 4; i++) {
                    float av = (kk == 0) ? a[i].x : (kk == 1) ? a[i].y : (kk == 2) ? a[i].z : a[i].w;
                    acc1[i][0] = fmaf(av, bv.x, acc1[i][0]);
                    acc1[i][1] = fmaf(av, bv.y, acc1[i][1]);
                    acc1[i][2] = fmaf(av, bv.z, acc1[i][2]);
                    acc1[i][3] = fmaf(av, bv.w, acc1[i][3]);
                }
            }
        }
        __syncthreads();

        #pragma unroll
        for (int j = 0; j < 4; j++) {
            float b = bn1[c0 + tx * 4 + j];
            #pragma unroll
            for (int i = 0; i < 4; i++)
                s_h1[(tx * 4 + j) * 68 + ty * 4 + i] = silu_f(acc1[i][j] + b);
        }
        for (int idx = tid; idx < 8192; idx += 256) {
            int k = idx >> 7, j = idx & 127;
            s_w2[idx] = Wn2[(c0 + k) * 128 + j];
        }
        __syncthreads();

        #pragma unroll 4
        for (int c = 0; c < 64; c++) {
            float4 a  = *(const float4*)&s_h1[c * 68 + ty * 4];
            float4 b0v = *(const float4*)&s_w2[c * 128 + tx * 8];
            float4 b1v = *(const float4*)&s_w2[c * 128 + tx * 8 + 4];
            #pragma unroll
            for (int i = 0; i < 4; i++) {
                float av = (i == 0) ? a.x : (i == 1) ? a.y : (i == 2) ? a.z : a.w;
                acc2[i][0] = fmaf(av, b0v.x, acc2[i][0]);
                acc2[i][1] = fmaf(av, b0v.y, acc2[i][1]);
                acc2[i][2] = fmaf(av, b0v.z, acc2[i][2]);
                acc2[i][3] = fmaf(av, b0v.w, acc2[i][3]);
                acc2[i][4] = fmaf(av, b1v.x, acc2[i][4]);
                acc2[i][5] = fmaf(av, b1v.y, acc2[i][5]);
                acc2[i][6] = fmaf(av, b1v.z, acc2[i][6]);
                acc2[i][7] = fmaf(av, b1v.w, acc2[i][7]);
            }
        }
        __syncthreads();
    }

    #pragma unroll
    for (int i = 0; i < 4; i++) {
        int g = b0 + ty * 4 + i;
        if (g < NN) {
            #pragma unroll
            for (int j = 0; j < 8; j++) {
                int col = tx * 8 + j;
                out[(long long)g * 131 + col] =
                    acc2[i][j] + bn2[col] + s_nin[(ty * 4 + i) * 196 + col];
            }
        }
    }
}

// ---------------------------------------------------------------------------
extern "C" void kernel_launch(void* const* d_in, const int* in_sizes, int n_in,
                              void* d_out, int out_size)
{
    const float* x   = (const float*)d_in[0];
    const void*  ei  = d_in[1];
    const float* We1 = (const float*)d_in[2];
    const float* be1 = (const float*)d_in[3];
    const float* We2 = (const float*)d_in[4];
    const float* be2 = (const float*)d_in[5];
    const float* Wc1 = (const float*)d_in[6];
    const float* bc1 = (const float*)d_in[7];
    const float* Wc2 = (const float*)d_in[8];
    const float* bc2 = (const float*)d_in[9];
    const float* Wn1 = (const float*)d_in[10];
    const float* bn1 = (const float*)d_in[11];
    const float* Wn2 = (const float*)d_in[12];
    const float* bn2 = (const float*)d_in[13];
    float* out = (float*)d_out;

    cudaFuncSetAttribute(edge_kernel, cudaFuncAttributeMaxDynamicSharedMemorySize, EDGE_SMEM_BYTES);
    cudaFuncSetAttribute(node_kernel, cudaFuncAttributeMaxDynamicSharedMemorySize, NODE_SMEM_BYTES);

    detect_kernel<<<1, 32>>>((const int*)ei);
    zero_kernel<<<1024, 256>>>();
    edge_kernel<<<(EE + 127) / 128, 256, EDGE_SMEM_BYTES>>>(
        x, ei, We1, be1, We2, be2, Wc1, bc1, Wc2, bc2);
    node_kernel<<<(NN + 63) / 64, 256, NODE_SMEM_BYTES>>>(
        x, Wn1, bn1, Wn2, bn2, out);
}

// round 4
// speedup vs baseline: 1.6705x; 1.6705x over previous
#include <cuda_runtime.h>
#include <cstdint>
#include <cstddef>

// Problem constants
#define NN 50000
#define EE 500000
// x row = 128 node feats + 3 coords = 131
// P table: row stride 1088 floats; P1 at col 0 (514 cols), P2 at col 544 (514 cols)
#define PSTRIDE 1088
#define P2OFF   544

__device__ float g_p[(size_t)NN * PSTRIDE]; // precomputed node @ [W_top | W_mid]
__device__ float g_m[NN * 64];   // segment-sum of m_ij
__device__ float g_w[NN];        // segment-sum of coord_w
__device__ float g_r[NN * 3];    // segment-sum of rel_coords
__device__ int   g_is64;         // edge_index dtype flag (1 = int64, 0 = int32)

__device__ __forceinline__ float silu_f(float v) {
    return __fdividef(v, 1.0f + __expf(-v));
}

// ---------------------------------------------------------------------------
__global__ void detect_kernel(const int* __restrict__ ei32) {
    if (threadIdx.x == 0 && blockIdx.x == 0) {
        int allzero = 1;
        #pragma unroll 1
        for (int i = 0; i < 64; i++) {
            if (ei32[2 * i + 1] != 0) { allzero = 0; break; }
        }
        g_is64 = allzero;
    }
}

__global__ void zero_kernel() {
    int stride = gridDim.x * blockDim.x;
    int i = blockIdx.x * blockDim.x + threadIdx.x;
    for (int k = i; k < NN * 64; k += stride) g_m[k] = 0.0f;
    for (int k = i; k < NN; k += stride) g_w[k] = 0.0f;
    for (int k = i; k < NN * 3; k += stride) g_r[k] = 0.0f;
}

// ---------------------------------------------------------------------------
// Precompute kernel: P[n, 0:514]   = node[n] @ We1[0:128, :]
//                    P[n, 544:1058]= node[n] @ We1[128:256, :]
// 64 nodes/block, 256 threads, col chunks of 64 over logical width 1088.
// Shared: s_x [64][132] (8448 fl) | s_w [128][64] (8192 fl) = 66560 bytes
// ---------------------------------------------------------------------------
#define PRE_SMEM_BYTES 66560

__global__ __launch_bounds__(256)
void pre_kernel(const float* __restrict__ x, const float* __restrict__ We1)
{
    extern __shared__ float sm[];
    float* s_x = sm;          // [64][132]
    float* s_w = sm + 8448;   // [128][64]

    const int tid  = threadIdx.x;
    const int lane = tid & 31;
    const int wrp  = tid >> 5;
    const int b0   = blockIdx.x * 64;

    for (int i = wrp; i < 64; i += 8) {
        int g = b0 + i;
        if (g < NN) {
            const float* xr = x + (size_t)g * 131;
            #pragma unroll
            for (int c = lane; c < 128; c += 32) s_x[i * 132 + c] = xr[c];
        } else {
            for (int c = lane; c < 128; c += 32) s_x[i * 132 + c] = 0.0f;
        }
    }
    __syncthreads();

    const int tx = tid & 15;   // 16 -> 4 cols each
    const int ty = tid >> 4;   // 16 -> 4 nodes each

    for (int chunk = 0; chunk < 17; chunk++) {
        int cw0 = chunk * 64;
        // load concatenated W chunk [128][64]
        for (int idx = tid; idx < 8192; idx += 256) {
            int k = idx >> 6, j = idx & 63;
            int c = cw0 + j;
            float v = 0.0f;
            if (c < 514)                     v = We1[k * 514 + c];
            else if (c >= P2OFF && c < 1058) v = We1[(128 + k) * 514 + (c - P2OFF)];
            s_w[idx] = v;
        }
        __syncthreads();

        float acc[4][4];
        #pragma unroll
        for (int i = 0; i < 4; i++)
            #pragma unroll
            for (int j = 0; j < 4; j++) acc[i][j] = 0.0f;

        for (int k = 0; k < 128; k += 4) {
            float4 a[4];
            #pragma unroll
            for (int i = 0; i < 4; i++)
                a[i] = *(const float4*)&s_x[(ty * 4 + i) * 132 + k];
            #pragma unroll
            for (int kk = 0; kk < 4; kk++) {
                float4 bv = *(const float4*)&s_w[(k + kk) * 64 + (tx << 2)];
                #pragma unroll
                for (int i = 0; i < 4; i++) {
                    float av = (kk == 0) ? a[i].x : (kk == 1) ? a[i].y : (kk == 2) ? a[i].z : a[i].w;
                    acc[i][0] = fmaf(av, bv.x, acc[i][0]);
                    acc[i][1] = fmaf(av, bv.y, acc[i][1]);
                    acc[i][2] = fmaf(av, bv.z, acc[i][2]);
                    acc[i][3] = fmaf(av, bv.w, acc[i][3]);
                }
            }
        }
        #pragma unroll
        for (int i = 0; i < 4; i++) {
            int g = b0 + ty * 4 + i;
            if (g < NN) {
                float4 v = make_float4(acc[i][0], acc[i][1], acc[i][2], acc[i][3]);
                *(float4*)&g_p[(size_t)g * PSTRIDE + cw0 + (tx << 2)] = v;
            }
        }
        __syncthreads();
    }
}

// ---------------------------------------------------------------------------
// Edge kernel: gather P -> h chunk (silu) -> GEMM2 (514->64) -> silu
//              -> GEMM3 (64->256) + silu -> dot W_c2 -> atomics
// 128 edges/block, 256 threads.
// Shared (floats):
//   s_h   [32][132]  off 0      (4224)
//   s_w2  [32][64]   off 4224   (2048)
//   s_m   [64][132]  off 6272   (8448)
//   s_wc  [64][32]   off 14720  (2048)
//   s_dst int[128]   off 16768
//   s_src int[128]   off 16896
//   s_dist[128]      off 17024
//   s_rel [128*3]    off 17152
//   s_bb  [32]       off 17536
//   s_wd  [32]       off 17568
// total 17600 floats = 70400 bytes
// ---------------------------------------------------------------------------
#define EDGE_SMEM_BYTES 70400

__global__ __launch_bounds__(256)
void edge_kernel(const float* __restrict__ x,
                 const void* __restrict__ ei_raw,
                 const float* __restrict__ We1, const float* __restrict__ be1,
                 const float* __restrict__ We2, const float* __restrict__ be2,
                 const float* __restrict__ Wc1, const float* __restrict__ bc1,
                 const float* __restrict__ Wc2, const float* __restrict__ bc2)
{
    extern __shared__ float sm[];
    float* s_h    = sm;                    // [32][132]
    float* s_w2   = sm + 4224;             // [32][64]
    float* s_m    = sm + 6272;             // [64][132]
    float* s_wc   = sm + 14720;            // [64][32]
    int*   s_dst  = (int*)(sm + 16768);
    int*   s_src  = (int*)(sm + 16896);
    float* s_dist = sm + 17024;
    float* s_rel  = sm + 17152;
    float* s_bb   = sm + 17536;
    float* s_wd   = sm + 17568;

    const int tid = threadIdx.x;
    const int is64 = g_is64;
    const long long* ei64 = (const long long*)ei_raw;
    const int*       ei32 = (const int*)ei_raw;

    // ---------------- gather edge meta ----------------
    if (tid < 128) {
        int e = tid;
        long long ge = (long long)blockIdx.x * 128 + e;
        int s = -1, d = -1;
        if (ge < EE) {
            if (is64) { s = (int)ei64[ge]; d = (int)ei64[EE + ge]; }
            else      { s = ei32[ge];      d = ei32[EE + ge]; }
            if (s < 0 || s >= NN || d < 0 || d >= NN) { s = -1; d = -1; }
        }
        float r0 = 0.0f, r1 = 0.0f, r2 = 0.0f, dist = 0.0f;
        if (d >= 0) {
            const float* xs = x + (size_t)s * 131;
            const float* xd = x + (size_t)d * 131;
            r0 = xs[128] - xd[128];
            r1 = xs[129] - xd[129];
            r2 = xs[130] - xd[130];
            dist = sqrtf(r0 * r0 + r1 * r1 + r2 * r2);
        }
        s_dst[e] = d;
        s_src[e] = (s >= 0) ? s : 0;
        s_dist[e] = dist;
        s_rel[e * 3 + 0] = r0;
        s_rel[e * 3 + 1] = r1;
        s_rel[e * 3 + 2] = r2;
    }
    __syncthreads();

    const int tx = tid & 15;       // 16 col/n threads
    const int ty = tid >> 4;       // 16 edge-groups of 8
    const int e0 = ty * 8;

    float macc[8][4];
    #pragma unroll
    for (int i = 0; i < 8; i++)
        #pragma unroll
        for (int j = 0; j < 4; j++) macc[i][j] = 0.0f;

    // ---------------- h chunks (gather) + GEMM2 over 514 in 32-col chunks --
    for (int chunk = 0; chunk < 17; chunk++) {
        int c0 = chunk * 32;
        // stage bias + dist-row of We1
        if (tid < 32) {
            int col = c0 + tid;
            s_bb[tid] = (col < 514) ? be1[col] : 0.0f;
            s_wd[tid] = (col < 514) ? We1[256 * 514 + col] : 0.0f;
        }
        // load We2 chunk [32][64]
        for (int idx = tid; idx < 2048; idx += 256) {
            int k = idx >> 6, j = idx & 63;
            int row = c0 + k;
            s_w2[idx] = (row < 514) ? We2[row * 64 + j] : 0.0f;
        }
        __syncthreads();

        // gather + silu -> s_h (col-major [c][e])
        #pragma unroll 1
        for (int iter = 0; iter < 8; iter++) {
            int task = iter * 256 + tid;
            int e  = task >> 4;
            int cp = task & 15;
            int c  = c0 + 2 * cp;
            int d  = s_dst[e];
            float2 p1 = make_float2(0.0f, 0.0f);
            float2 p2 = make_float2(0.0f, 0.0f);
            if (d >= 0) {
                int s = s_src[e];
                p1 = *(const float2*)&g_p[(size_t)d * PSTRIDE + c];
                p2 = *(const float2*)&g_p[(size_t)s * PSTRIDE + P2OFF + c];
            }
            float dist = s_dist[e];
            float h0 = silu_f(p1.x + p2.x + dist * s_wd[2 * cp]     + s_bb[2 * cp]);
            float h1 = silu_f(p1.y + p2.y + dist * s_wd[2 * cp + 1] + s_bb[2 * cp + 1]);
            if (d < 0) { h0 = 0.0f; h1 = 0.0f; }
            s_h[(2 * cp)     * 132 + e] = h0;
            s_h[(2 * cp + 1) * 132 + e] = h1;
        }
        __syncthreads();

        // GEMM2: m += h_chunk @ We2_chunk
        #pragma unroll 4
        for (int c = 0; c < 32; c++) {
            float4 a0 = *(const float4*)&s_h[c * 132 + e0];
            float4 a1 = *(const float4*)&s_h[c * 132 + e0 + 4];
            float4 bv = *(const float4*)&s_w2[c * 64 + (tx << 2)];
            #pragma unroll
            for (int j = 0; j < 4; j++) {
                float bj = (j == 0) ? bv.x : (j == 1) ? bv.y : (j == 2) ? bv.z : bv.w;
                macc[0][j] = fmaf(a0.x, bj, macc[0][j]);
                macc[1][j] = fmaf(a0.y, bj, macc[1][j]);
                macc[2][j] = fmaf(a0.z, bj, macc[2][j]);
                macc[3][j] = fmaf(a0.w, bj, macc[3][j]);
                macc[4][j] = fmaf(a1.x, bj, macc[4][j]);
                macc[5][j] = fmaf(a1.y, bj, macc[5][j]);
                macc[6][j] = fmaf(a1.z, bj, macc[6][j]);
                macc[7][j] = fmaf(a1.w, bj, macc[7][j]);
            }
        }
        __syncthreads();
    }

    // ---------------- m_ij = silu(m + b_e2); store + atomic scatter --------
    float mval[8][4];
    #pragma unroll
    for (int j = 0; j < 4; j++) {
        float b = be2[tx * 4 + j];
        #pragma unroll
        for (int i = 0; i < 8; i++) mval[i][j] = silu_f(macc[i][j] + b);
    }
    #pragma unroll
    for (int j = 0; j < 4; j++)
        #pragma unroll
        for (int i = 0; i < 8; i++)
            s_m[(tx * 4 + j) * 132 + e0 + i] = mval[i][j];
    #pragma unroll
    for (int i = 0; i < 8; i++) {
        int d = s_dst[e0 + i];
        if (d >= 0) {
            #pragma unroll
            for (int j = 0; j < 4; j++)
                atomicAdd(&g_m[d * 64 + tx * 4 + j], mval[i][j]);
        }
    }
    __syncthreads();

    // ---------------- GEMM3 (64->256) + silu + dot W_c2 --------------------
    float cw[8];
    #pragma unroll
    for (int i = 0; i < 8; i++) cw[i] = 0.0f;

    for (int c0 = 0; c0 < 256; c0 += 32) {
        for (int idx = tid; idx < 2048; idx += 256) {
            int k = idx >> 5, j = idx & 31;
            s_wc[idx] = Wc1[k * 256 + c0 + j];
        }
        __syncthreads();

        float acc[8][2];
        #pragma unroll
        for (int i = 0; i < 8; i++) { acc[i][0] = 0.0f; acc[i][1] = 0.0f; }

        for (int k = 0; k < 64; k += 4) {
            #pragma unroll
            for (int kk = 0; kk < 4; kk++) {
                float4 a0 = *(const float4*)&s_m[(k + kk) * 132 + e0];
                float4 a1 = *(const float4*)&s_m[(k + kk) * 132 + e0 + 4];
                float2 bv = *(const float2*)&s_wc[(k + kk) * 32 + (tx << 1)];
                acc[0][0] = fmaf(a0.x, bv.x, acc[0][0]); acc[0][1] = fmaf(a0.x, bv.y, acc[0][1]);
                acc[1][0] = fmaf(a0.y, bv.x, acc[1][0]); acc[1][1] = fmaf(a0.y, bv.y, acc[1][1]);
                acc[2][0] = fmaf(a0.z, bv.x, acc[2][0]); acc[2][1] = fmaf(a0.z, bv.y, acc[2][1]);
                acc[3][0] = fmaf(a0.w, bv.x, acc[3][0]); acc[3][1] = fmaf(a0.w, bv.y, acc[3][1]);
                acc[4][0] = fmaf(a1.x, bv.x, acc[4][0]); acc[4][1] = fmaf(a1.x, bv.y, acc[4][1]);
                acc[5][0] = fmaf(a1.y, bv.x, acc[5][0]); acc[5][1] = fmaf(a1.y, bv.y, acc[5][1]);
                acc[6][0] = fmaf(a1.z, bv.x, acc[6][0]); acc[6][1] = fmaf(a1.z, bv.y, acc[6][1]);
                acc[7][0] = fmaf(a1.w, bv.x, acc[7][0]); acc[7][1] = fmaf(a1.w, bv.y, acc[7][1]);
            }
        }
        float bb0 = bc1[c0 + tx * 2], bb1 = bc1[c0 + tx * 2 + 1];
        float w20 = Wc2[c0 + tx * 2], w21 = Wc2[c0 + tx * 2 + 1];
        #pragma unroll
        for (int i = 0; i < 8; i++)
            cw[i] += silu_f(acc[i][0] + bb0) * w20 + silu_f(acc[i][1] + bb1) * w21;
        __syncthreads();
    }

    // reduce coord_w over 16 tx lanes (xor stays within 16-lane halves)
    #pragma unroll
    for (int off = 8; off >= 1; off >>= 1)
        #pragma unroll
        for (int i = 0; i < 8; i++)
            cw[i] += __shfl_xor_sync(0xffffffffu, cw[i], off);

    if (tx == 0) {
        float bc2v = bc2[0];
        #pragma unroll
        for (int i = 0; i < 8; i++) {
            int d = s_dst[e0 + i];
            if (d >= 0) {
                atomicAdd(&g_w[d], cw[i] + bc2v);
                atomicAdd(&g_r[d * 3 + 0], s_rel[(e0 + i) * 3 + 0]);
                atomicAdd(&g_r[d * 3 + 1], s_rel[(e0 + i) * 3 + 1]);
                atomicAdd(&g_r[d * 3 + 2], s_rel[(e0 + i) * 3 + 2]);
            }
        }
    }
}

// ---------------------------------------------------------------------------
// Node kernel: coords_out + fused MLP (192->256 silu ->128) + residual
// 64 nodes/block, 256 threads, 32-col chunks (SMEM 99840B -> 2 blocks/SM).
// Shared: s_nin [64][196] (12544) | s_w1 [192][32] (6144)
//         | s_h1 [32][68] (2176) | s_w2 [32][128] (4096) = 24960 floats
// ---------------------------------------------------------------------------
#define NODE_SMEM_BYTES 99840

__global__ __launch_bounds__(256)
void node_kernel(const float* __restrict__ x,
                 const float* __restrict__ Wn1, const float* __restrict__ bn1,
                 const float* __restrict__ Wn2, const float* __restrict__ bn2,
                 float* __restrict__ out)
{
    extern __shared__ float sm[];
    float* s_nin = sm;              // [64][196]
    float* s_w1  = sm + 12544;      // [192][32]
    float* s_h1  = sm + 18688;      // [32][68]
    float* s_w2  = sm + 20864;      // [32][128]

    const int tid  = threadIdx.x;
    const int lane = tid & 31;
    const int wrp  = tid >> 5;
    const int b0   = blockIdx.x * 64;

    for (int i = wrp; i < 64; i += 8) {
        int g = b0 + i;
        if (g < NN) {
            const float* xr = x + (size_t)g * 131;
            #pragma unroll
            for (int c = lane; c < 128; c += 32) s_nin[i * 196 + c] = xr[c];
            #pragma unroll
            for (int c = lane; c < 64; c += 32) s_nin[i * 196 + 128 + c] = g_m[g * 64 + c];
            if (lane < 4) s_nin[i * 196 + 192 + lane] = 0.0f;
            if (lane < 3)
                out[(size_t)g * 131 + 128 + lane] = xr[128 + lane] + g_w[g] * g_r[g * 3 + lane];
        } else {
            for (int c = lane; c < 196; c += 32) s_nin[i * 196 + c] = 0.0f;
        }
    }
    __syncthreads();

    const int tx = tid & 15;
    const int ty = tid >> 4;

    float acc2[4][8];
    #pragma unroll
    for (int i = 0; i < 4; i++)
        #pragma unroll
        for (int j = 0; j < 8; j++) acc2[i][j] = 0.0f;

    for (int c0 = 0; c0 < 256; c0 += 32) {
        for (int idx = tid; idx < 6144; idx += 256) {
            int k = idx >> 5, j = idx & 31;
            s_w1[idx] = Wn1[k * 256 + c0 + j];
        }
        __syncthreads();

        float acc1[4][2];
        #pragma unroll
        for (int i = 0; i < 4; i++) { acc1[i][0] = 0.0f; acc1[i][1] = 0.0f; }

        for (int k = 0; k < 192; k += 4) {
            float4 a[4];
            #pragma unroll
            for (int i = 0; i < 4; i++)
                a[i] = *(const float4*)&s_nin[(ty * 4 + i) * 196 + k];
            #pragma unroll
            for (int kk = 0; kk < 4; kk++) {
                float2 bv = *(const float2*)&s_w1[(k + kk) * 32 + (tx << 1)];
                #pragma unroll
                for (int i = 0; i < 4; i++) {
                    float av = (kk == 0) ? a[i].x : (kk == 1) ? a[i].y : (kk == 2) ? a[i].z : a[i].w;
                    acc1[i][0] = fmaf(av, bv.x, acc1[i][0]);
                    acc1[i][1] = fmaf(av, bv.y, acc1[i][1]);
                }
            }
        }
        __syncthreads();

        #pragma unroll
        for (int jj = 0; jj < 2; jj++) {
            float b = bn1[c0 + tx * 2 + jj];
            #pragma unroll
            for (int i = 0; i < 4; i++)
                s_h1[(tx * 2 + jj) * 68 + ty * 4 + i] = silu_f(acc1[i][jj] + b);
        }
        for (int idx = tid; idx < 4096; idx += 256) {
            int k = idx >> 7, j = idx & 127;
            s_w2[idx] = Wn2[(c0 + k) * 128 + j];
        }
        __syncthreads();

        #pragma unroll 4
        for (int c = 0; c < 32; c++) {
            float4 a   = *(const float4*)&s_h1[c * 68 + ty * 4];
            float4 b0v = *(const float4*)&s_w2[c * 128 + tx * 8];
            float4 b1v = *(const float4*)&s_w2[c * 128 + tx * 8 + 4];
            #pragma unroll
            for (int i = 0; i < 4; i++) {
                float av = (i == 0) ? a.x : (i == 1) ? a.y : (i == 2) ? a.z : a.w;
                acc2[i][0] = fmaf(av, b0v.x, acc2[i][0]);
                acc2[i][1] = fmaf(av, b0v.y, acc2[i][1]);
                acc2[i][2] = fmaf(av, b0v.z, acc2[i][2]);
                acc2[i][3] = fmaf(av, b0v.w, acc2[i][3]);
                acc2[i][4] = fmaf(av, b1v.x, acc2[i][4]);
                acc2[i][5] = fmaf(av, b1v.y, acc2[i][5]);
                acc2[i][6] = fmaf(av, b1v.z, acc2[i][6]);
                acc2[i][7] = fmaf(av, b1v.w, acc2[i][7]);
            }
        }
        __syncthreads();
    }

    #pragma unroll
    for (int i = 0; i < 4; i++) {
        int g = b0 + ty * 4 + i;
        if (g < NN) {
            #pragma unroll
            for (int j = 0; j < 8; j++) {
                int col = tx * 8 + j;
                out[(size_t)g * 131 + col] =
                    acc2[i][j] + bn2[col] + s_nin[(ty * 4 + i) * 196 + col];
            }
        }
    }
}

// ---------------------------------------------------------------------------
extern "C" void kernel_launch(void* const* d_in, const int* in_sizes, int n_in,
                              void* d_out, int out_size)
{
    const float* x   = (const float*)d_in[0];
    const void*  ei  = d_in[1];
    const float* We1 = (const float*)d_in[2];
    const float* be1 = (const float*)d_in[3];
    const float* We2 = (const float*)d_in[4];
    const float* be2 = (const float*)d_in[5];
    const float* Wc1 = (const float*)d_in[6];
    const float* bc1 = (const float*)d_in[7];
    const float* Wc2 = (const float*)d_in[8];
    const float* bc2 = (const float*)d_in[9];
    const float* Wn1 = (const float*)d_in[10];
    const float* bn1 = (const float*)d_in[11];
    const float* Wn2 = (const float*)d_in[12];
    const float* bn2 = (const float*)d_in[13];
    float* out = (float*)d_out;

    cudaFuncSetAttribute(pre_kernel,  cudaFuncAttributeMaxDynamicSharedMemorySize, PRE_SMEM_BYTES);
    cudaFuncSetAttribute(edge_kernel, cudaFuncAttributeMaxDynamicSharedMemorySize, EDGE_SMEM_BYTES);
    cudaFuncSetAttribute(node_kernel, cudaFuncAttributeMaxDynamicSharedMemorySize, NODE_SMEM_BYTES);

    detect_kernel<<<1, 32>>>((const int*)ei);
    zero_kernel<<<1024, 256>>>();
    pre_kernel<<<(NN + 63) / 64, 256, PRE_SMEM_BYTES>>>(x, We1);
    edge_kernel<<<(EE + 127) / 128, 256, EDGE_SMEM_BYTES>>>(
        x, ei, We1, be1, We2, be2, Wc1, bc1, Wc2, bc2);
    node_kernel<<<(NN + 63) / 64, 256, NODE_SMEM_BYTES>>>(
        x, Wn1, bn1, Wn2, bn2, out);
}

// round 8
// speedup vs baseline: 2.5720x; 1.5396x over previous
#include <cuda_runtime.h>
#include <cstdint>
#include <cstddef>

// Problem constants
#define NN 50000
#define EE 500000
// x row = 128 node feats + 3 coords = 131
// P table: row stride 1088 floats; P1 at col 0 (514 cols), P2 at col 544 (514 cols)
#define PSTRIDE 1088
#define P2OFF   544

__device__ float g_p[(size_t)NN * PSTRIDE]; // precomputed node @ [W_top | W_mid]
__device__ float g_m[NN * 64];   // segment-sum of m_ij
__device__ float g_w[NN];        // segment-sum of coord_w
__device__ float g_r[NN * 3];    // segment-sum of rel_coords
__device__ int   g_is64;         // edge_index dtype flag (1 = int64, 0 = int32)

__device__ __forceinline__ float silu_f(float v) {
    return __fdividef(v, 1.0f + __expf(-v));
}

// ---- packed fp32x2 helpers (Blackwell FFMA2) ------------------------------
typedef unsigned long long u64t;

__device__ __forceinline__ void ffma2(u64t& d, u64t a, u64t b) {
    asm("fma.rn.f32x2 %0, %1, %2, %3;" : "=l"(d) : "l"(a), "l"(b), "l"(d));
}
__device__ __forceinline__ u64t pack2s(float v) {   // (v, v)
    u64t r;
    unsigned int u = __float_as_uint(v);
    asm("mov.b64 %0, {%1, %2};" : "=l"(r) : "r"(u), "r"(u));
    return r;
}
__device__ __forceinline__ float2 unpack2(u64t v) {
    unsigned int lo, hi;
    asm("mov.b64 {%0, %1}, %2;" : "=r"(lo), "=r"(hi) : "l"(v));
    return make_float2(__uint_as_float(lo), __uint_as_float(hi));
}

// ---------------------------------------------------------------------------
__global__ void detect_kernel(const int* __restrict__ ei32) {
    if (threadIdx.x == 0 && blockIdx.x == 0) {
        int allzero = 1;
        #pragma unroll 1
        for (int i = 0; i < 64; i++) {
            if (ei32[2 * i + 1] != 0) { allzero = 0; break; }
        }
        g_is64 = allzero;
    }
}

__global__ void zero_kernel() {
    int stride = gridDim.x * blockDim.x;
    int i = blockIdx.x * blockDim.x + threadIdx.x;
    for (int k = i; k < NN * 64; k += stride) g_m[k] = 0.0f;
    for (int k = i; k < NN; k += stride) g_w[k] = 0.0f;
    for (int k = i; k < NN * 3; k += stride) g_r[k] = 0.0f;
}

// ---------------------------------------------------------------------------
// Precompute kernel: P[n, 0:514]   = node[n] @ We1[0:128, :]
//                    P[n, 544:1058]= node[n] @ We1[128:256, :]
// ---------------------------------------------------------------------------
#define PRE_SMEM_BYTES 66560

__global__ __launch_bounds__(256)
void pre_kernel(const float* __restrict__ x, const float* __restrict__ We1)
{
    extern __shared__ float sm[];
    float* s_x = sm;          // [64][132]
    float* s_w = sm + 8448;   // [128][64]

    const int tid  = threadIdx.x;
    const int lane = tid & 31;
    const int wrp  = tid >> 5;
    const int b0   = blockIdx.x * 64;

    for (int i = wrp; i < 64; i += 8) {
        int g = b0 + i;
        if (g < NN) {
            const float* xr = x + (size_t)g * 131;
            #pragma unroll
            for (int c = lane; c < 128; c += 32) s_x[i * 132 + c] = xr[c];
        } else {
            for (int c = lane; c < 128; c += 32) s_x[i * 132 + c] = 0.0f;
        }
    }
    __syncthreads();

    const int tx = tid & 15;   // 16 -> 4 cols each
    const int ty = tid >> 4;   // 16 -> 4 nodes each

    for (int chunk = 0; chunk < 17; chunk++) {
        int cw0 = chunk * 64;
        for (int idx = tid; idx < 8192; idx += 256) {
            int k = idx >> 6, j = idx & 63;
            int c = cw0 + j;
            float v = 0.0f;
            if (c < 514)                     v = We1[k * 514 + c];
            else if (c >= P2OFF && c < 1058) v = We1[(128 + k) * 514 + (c - P2OFF)];
            s_w[idx] = v;
        }
        __syncthreads();

        u64t accp[4][2];
        #pragma unroll
        for (int i = 0; i < 4; i++) { accp[i][0] = 0ull; accp[i][1] = 0ull; }

        for (int k = 0; k < 128; k += 4) {
            float4 a[4];
            #pragma unroll
            for (int i = 0; i < 4; i++)
                a[i] = *(const float4*)&s_x[(ty * 4 + i) * 132 + k];
            #pragma unroll
            for (int kk = 0; kk < 4; kk++) {
                ulonglong2 B = *(const ulonglong2*)&s_w[(k + kk) * 64 + (tx << 2)];
                #pragma unroll
                for (int i = 0; i < 4; i++) {
                    float av = (kk == 0) ? a[i].x : (kk == 1) ? a[i].y : (kk == 2) ? a[i].z : a[i].w;
                    u64t Ap = pack2s(av);
                    ffma2(accp[i][0], Ap, B.x);
                    ffma2(accp[i][1], Ap, B.y);
                }
            }
        }
        #pragma unroll
        for (int i = 0; i < 4; i++) {
            int g = b0 + ty * 4 + i;
            if (g < NN) {
                float2 v0 = unpack2(accp[i][0]);
                float2 v1 = unpack2(accp[i][1]);
                float4 v = make_float4(v0.x, v0.y, v1.x, v1.y);
                *(float4*)&g_p[(size_t)g * PSTRIDE + cw0 + (tx << 2)] = v;
            }
        }
        __syncthreads();
    }
}

// ---------------------------------------------------------------------------
// Edge kernel: gather P -> h chunk (silu) -> GEMM2 (514->64) -> silu
//              -> GEMM3 (64->256) + silu -> dot W_c2 -> atomics
// 128 edges/block, 256 threads. SMEM = 70400 bytes.
// ---------------------------------------------------------------------------
#define EDGE_SMEM_BYTES 70400

__global__ __launch_bounds__(256)
void edge_kernel(const float* __restrict__ x,
                 const void* __restrict__ ei_raw,
                 const float* __restrict__ We1, const float* __restrict__ be1,
                 const float* __restrict__ We2, const float* __restrict__ be2,
                 const float* __restrict__ Wc1, const float* __restrict__ bc1,
                 const float* __restrict__ Wc2, const float* __restrict__ bc2)
{
    extern __shared__ float sm[];
    float* s_h    = sm;                    // [32][132]
    float* s_w2   = sm + 4224;             // [32][64]
    float* s_m    = sm + 6272;             // [64][132]
    float* s_wc   = sm + 14720;            // [64][32]
    int*   s_dst  = (int*)(sm + 16768);
    int*   s_src  = (int*)(sm + 16896);
    float* s_dist = sm + 17024;
    float* s_rel  = sm + 17152;
    float* s_bb   = sm + 17536;
    float* s_wd   = sm + 17568;

    const int tid = threadIdx.x;
    const int is64 = g_is64;
    const long long* ei64 = (const long long*)ei_raw;
    const int*       ei32 = (const int*)ei_raw;

    // ---------------- gather edge meta ----------------
    if (tid < 128) {
        int e = tid;
        long long ge = (long long)blockIdx.x * 128 + e;
        int s = -1, d = -1;
        if (ge < EE) {
            if (is64) { s = (int)ei64[ge]; d = (int)ei64[EE + ge]; }
            else      { s = ei32[ge];      d = ei32[EE + ge]; }
            if (s < 0 || s >= NN || d < 0 || d >= NN) { s = -1; d = -1; }
        }
        float r0 = 0.0f, r1 = 0.0f, r2 = 0.0f, dist = 0.0f;
        if (d >= 0) {
            const float* xs = x + (size_t)s * 131;
            const float* xd = x + (size_t)d * 131;
            r0 = xs[128] - xd[128];
            r1 = xs[129] - xd[129];
            r2 = xs[130] - xd[130];
            dist = sqrtf(r0 * r0 + r1 * r1 + r2 * r2);
        }
        s_dst[e] = d;
        s_src[e] = (s >= 0) ? s : 0;
        s_dist[e] = dist;
        s_rel[e * 3 + 0] = r0;
        s_rel[e * 3 + 1] = r1;
        s_rel[e * 3 + 2] = r2;
    }
    __syncthreads();

    const int tx = tid & 15;       // 16 col/n threads
    const int ty = tid >> 4;       // 16 edge-groups of 8
    const int e0 = ty * 8;

    u64t macc[4][4];               // edge-pair p x n-col j
    #pragma unroll
    for (int p = 0; p < 4; p++)
        #pragma unroll
        for (int j = 0; j < 4; j++) macc[p][j] = 0ull;

    // ---------------- h chunks (gather) + GEMM2 over 514 in 32-col chunks --
    for (int chunk = 0; chunk < 17; chunk++) {
        int c0 = chunk * 32;
        if (tid < 32) {
            int col = c0 + tid;
            s_bb[tid] = (col < 514) ? be1[col] : 0.0f;
            s_wd[tid] = (col < 514) ? We1[256 * 514 + col] : 0.0f;
        }
        for (int idx = tid; idx < 2048; idx += 256) {
            int k = idx >> 6, j = idx & 63;
            int row = c0 + k;
            s_w2[idx] = (row < 514) ? We2[row * 64 + j] : 0.0f;
        }
        __syncthreads();

        // gather + silu -> s_h (col-major [c][e]); unroll for MLP
        #pragma unroll 2
        for (int iter = 0; iter < 8; iter++) {
            int task = iter * 256 + tid;
            int e  = task >> 4;
            int cp = task & 15;
            int c  = c0 + 2 * cp;
            int d  = s_dst[e];
            float2 p1 = make_float2(0.0f, 0.0f);
            float2 p2 = make_float2(0.0f, 0.0f);
            if (d >= 0) {
                int s = s_src[e];
                p1 = *(const float2*)&g_p[(size_t)d * PSTRIDE + c];
                p2 = *(const float2*)&g_p[(size_t)s * PSTRIDE + P2OFF + c];
            }
            float dist = s_dist[e];
            float h0 = silu_f(p1.x + p2.x + dist * s_wd[2 * cp]     + s_bb[2 * cp]);
            float h1 = silu_f(p1.y + p2.y + dist * s_wd[2 * cp + 1] + s_bb[2 * cp + 1]);
            if (d < 0) { h0 = 0.0f; h1 = 0.0f; }
            s_h[(2 * cp)     * 132 + e] = h0;
            s_h[(2 * cp + 1) * 132 + e] = h1;
        }
        __syncthreads();

        // GEMM2 (FFMA2): m += h_chunk @ We2_chunk
        #pragma unroll 4
        for (int c = 0; c < 32; c++) {
            ulonglong2 A0 = *(const ulonglong2*)&s_h[c * 132 + e0];      // pairs 0,1
            ulonglong2 A1 = *(const ulonglong2*)&s_h[c * 132 + e0 + 4];  // pairs 2,3
            float4 bv = *(const float4*)&s_w2[c * 64 + (tx << 2)];
            u64t B0 = pack2s(bv.x), B1 = pack2s(bv.y), B2 = pack2s(bv.z), B3 = pack2s(bv.w);
            ffma2(macc[0][0], A0.x, B0); ffma2(macc[0][1], A0.x, B1);
            ffma2(macc[0][2], A0.x, B2); ffma2(macc[0][3], A0.x, B3);
            ffma2(macc[1][0], A0.y, B0); ffma2(macc[1][1], A0.y, B1);
            ffma2(macc[1][2], A0.y, B2); ffma2(macc[1][3], A0.y, B3);
            ffma2(macc[2][0], A1.x, B0); ffma2(macc[2][1], A1.x, B1);
            ffma2(macc[2][2], A1.x, B2); ffma2(macc[2][3], A1.x, B3);
            ffma2(macc[3][0], A1.y, B0); ffma2(macc[3][1], A1.y, B1);
            ffma2(macc[3][2], A1.y, B2); ffma2(macc[3][3], A1.y, B3);
        }
        __syncthreads();
    }

    // ---------------- m_ij = silu(m + b_e2); store + atomic scatter --------
    float mval[8][4];
    #pragma unroll
    for (int j = 0; j < 4; j++) {
        float b = be2[tx * 4 + j];
        #pragma unroll
        for (int p = 0; p < 4; p++) {
            float2 v = unpack2(macc[p][j]);
            mval[2 * p][j]     = silu_f(v.x + b);
            mval[2 * p + 1][j] = silu_f(v.y + b);
        }
    }
    #pragma unroll
    for (int j = 0; j < 4; j++)
        #pragma unroll
        for (int i = 0; i < 8; i++)
            s_m[(tx * 4 + j) * 132 + e0 + i] = mval[i][j];
    #pragma unroll
    for (int i = 0; i < 8; i++) {
        int d = s_dst[e0 + i];
        if (d >= 0) {
            #pragma unroll
            for (int j = 0; j < 4; j++)
                atomicAdd(&g_m[d * 64 + tx * 4 + j], mval[i][j]);
        }
    }
    __syncthreads();

    // ---------------- GEMM3 (64->256) + silu + dot W_c2 (FFMA2) ------------
    float cw[8];
    #pragma unroll
    for (int i = 0; i < 8; i++) cw[i] = 0.0f;

    for (int c0 = 0; c0 < 256; c0 += 32) {
        for (int idx = tid; idx < 2048; idx += 256) {
            int k = idx >> 5, j = idx & 31;
            s_wc[idx] = Wc1[k * 256 + c0 + j];
        }
        __syncthreads();

        u64t acc[4][2];
        #pragma unroll
        for (int p = 0; p < 4; p++) { acc[p][0] = 0ull; acc[p][1] = 0ull; }

        for (int k = 0; k < 64; k += 4) {
            #pragma unroll
            for (int kk = 0; kk < 4; kk++) {
                ulonglong2 A0 = *(const ulonglong2*)&s_m[(k + kk) * 132 + e0];
                ulonglong2 A1 = *(const ulonglong2*)&s_m[(k + kk) * 132 + e0 + 4];
                float2 bv = *(const float2*)&s_wc[(k + kk) * 32 + (tx << 1)];
                u64t B0 = pack2s(bv.x), B1 = pack2s(bv.y);
                ffma2(acc[0][0], A0.x, B0); ffma2(acc[0][1], A0.x, B1);
                ffma2(acc[1][0], A0.y, B0); ffma2(acc[1][1], A0.y, B1);
                ffma2(acc[2][0], A1.x, B0); ffma2(acc[2][1], A1.x, B1);
                ffma2(acc[3][0], A1.y, B0); ffma2(acc[3][1], A1.y, B1);
            }
        }
        float bb0 = bc1[c0 + tx * 2], bb1 = bc1[c0 + tx * 2 + 1];
        float w20 = Wc2[c0 + tx * 2], w21 = Wc2[c0 + tx * 2 + 1];
        #pragma unroll
        for (int p = 0; p < 4; p++) {
            float2 v0 = unpack2(acc[p][0]);
            float2 v1 = unpack2(acc[p][1]);
            cw[2 * p]     += silu_f(v0.x + bb0) * w20 + silu_f(v1.x + bb1) * w21;
            cw[2 * p + 1] += silu_f(v0.y + bb0) * w20 + silu_f(v1.y + bb1) * w21;
        }
        __syncthreads();
    }

    // reduce coord_w over 16 tx lanes (xor stays within 16-lane halves)
    #pragma unroll
    for (int off = 8; off >= 1; off >>= 1)
        #pragma unroll
        for (int i = 0; i < 8; i++)
            cw[i] += __shfl_xor_sync(0xffffffffu, cw[i], off);

    if (tx == 0) {
        float bc2v = bc2[0];
        #pragma unroll
        for (int i = 0; i < 8; i++) {
            int d = s_dst[e0 + i];
            if (d >= 0) {
                atomicAdd(&g_w[d], cw[i] + bc2v);
                atomicAdd(&g_r[d * 3 + 0], s_rel[(e0 + i) * 3 + 0]);
                atomicAdd(&g_r[d * 3 + 1], s_rel[(e0 + i) * 3 + 1]);
                atomicAdd(&g_r[d * 3 + 2], s_rel[(e0 + i) * 3 + 2]);
            }
        }
    }
}

// ---------------------------------------------------------------------------
// Node kernel: coords_out + fused MLP (192->256 silu ->128) + residual
// ---------------------------------------------------------------------------
#define NODE_SMEM_BYTES 99840

__global__ __launch_bounds__(256)
void node_kernel(const float* __restrict__ x,
                 const float* __restrict__ Wn1, const float* __restrict__ bn1,
                 const float* __restrict__ Wn2, const float* __restrict__ bn2,
                 float* __restrict__ out)
{
    extern __shared__ float sm[];
    float* s_nin = sm;              // [64][196]
    float* s_w1  = sm + 12544;      // [192][32]
    float* s_h1  = sm + 18688;      // [32][68]
    float* s_w2  = sm + 20864;      // [32][128]

    const int tid  = threadIdx.x;
    const int lane = tid & 31;
    const int wrp  = tid >> 5;
    const int b0   = blockIdx.x * 64;

    for (int i = wrp; i < 64; i += 8) {
        int g = b0 + i;
        if (g < NN) {
            const float* xr = x + (size_t)g * 131;
            #pragma unroll
            for (int c = lane; c < 128; c += 32) s_nin[i * 196 + c] = xr[c];
            #pragma unroll
            for (int c = lane; c < 64; c += 32) s_nin[i * 196 + 128 + c] = g_m[g * 64 + c];
            if (lane < 4) s_nin[i * 196 + 192 + lane] = 0.0f;
            if (lane < 3)
                out[(size_t)g * 131 + 128 + lane] = xr[128 + lane] + g_w[g] * g_r[g * 3 + lane];
        } else {
            for (int c = lane; c < 196; c += 32) s_nin[i * 196 + c] = 0.0f;
        }
    }
    __syncthreads();

    const int tx = tid & 15;
    const int ty = tid >> 4;

    u64t pacc[4][4];   // node i x col-pair q
    #pragma unroll
    for (int i = 0; i < 4; i++)
        #pragma unroll
        for (int q = 0; q < 4; q++) pacc[i][q] = 0ull;

    for (int c0 = 0; c0 < 256; c0 += 32) {
        for (int idx = tid; idx < 6144; idx += 256) {
            int k = idx >> 5, j = idx & 31;
            s_w1[idx] = Wn1[k * 256 + c0 + j];
        }
        __syncthreads();

        u64t acc1p[4];
        #pragma unroll
        for (int i = 0; i < 4; i++) acc1p[i] = 0ull;

        for (int k = 0; k < 192; k += 4) {
            float4 a[4];
            #pragma unroll
            for (int i = 0; i < 4; i++)
                a[i] = *(const float4*)&s_nin[(ty * 4 + i) * 196 + k];
            #pragma unroll
            for (int kk = 0; kk < 4; kk++) {
                u64t bp = *(const u64t*)&s_w1[(k + kk) * 32 + (tx << 1)];
                #pragma unroll
                for (int i = 0; i < 4; i++) {
                    float av = (kk == 0) ? a[i].x : (kk == 1) ? a[i].y : (kk == 2) ? a[i].z : a[i].w;
                    ffma2(acc1p[i], pack2s(av), bp);
                }
            }
        }
        __syncthreads();

        {
            float bjx = bn1[c0 + tx * 2];
            float bjy = bn1[c0 + tx * 2 + 1];
            #pragma unroll
            for (int i = 0; i < 4; i++) {
                float2 v = unpack2(acc1p[i]);
                s_h1[(tx * 2)     * 68 + ty * 4 + i] = silu_f(v.x + bjx);
                s_h1[(tx * 2 + 1) * 68 + ty * 4 + i] = silu_f(v.y + bjy);
            }
        }
        for (int idx = tid; idx < 4096; idx += 256) {
            int k = idx >> 7, j = idx & 127;
            s_w2[idx] = Wn2[(c0 + k) * 128 + j];
        }
        __syncthreads();

        #pragma unroll 4
        for (int c = 0; c < 32; c++) {
            float4 a = *(const float4*)&s_h1[c * 68 + ty * 4];
            ulonglong2 B0 = *(const ulonglong2*)&s_w2[c * 128 + tx * 8];
            ulonglong2 B1 = *(const ulonglong2*)&s_w2[c * 128 + tx * 8 + 4];
            #pragma unroll
            for (int i = 0; i < 4; i++) {
                float av = (i == 0) ? a.x : (i == 1) ? a.y : (i == 2) ? a.z : a.w;
                u64t Ap = pack2s(av);
                ffma2(pacc[i][0], Ap, B0.x);
                ffma2(pacc[i][1], Ap, B0.y);
                ffma2(pacc[i][2], Ap, B1.x);
                ffma2(pacc[i][3], Ap, B1.y);
            }
        }
        __syncthreads();
    }

    #pragma unroll
    for (int i = 0; i < 4; i++) {
        int g = b0 + ty * 4 + i;
        if (g < NN) {
            #pragma unroll
            for (int q = 0; q < 4; q++) {
                float2 v = unpack2(pacc[i][q]);
                int col = tx * 8 + 2 * q;
                out[(size_t)g * 131 + col] =
                    v.x + bn2[col] + s_nin[(ty * 4 + i) * 196 + col];
                out[(size_t)g * 131 + col + 1] =
                    v.y + bn2[col + 1] + s_nin[(ty * 4 + i) * 196 + col + 1];
            }
        }
    }
}

// ---------------------------------------------------------------------------
extern "C" void kernel_launch(void* const* d_in, const int* in_sizes, int n_in,
                              void* d_out, int out_size)
{
    const float* x   = (const float*)d_in[0];
    const void*  ei  = d_in[1];
    const float* We1 = (const float*)d_in[2];
    const float* be1 = (const float*)d_in[3];
    const float* We2 = (const float*)d_in[4];
    const float* be2 = (const float*)d_in[5];
    const float* Wc1 = (const float*)d_in[6];
    const float* bc1 = (const float*)d_in[7];
    const float* Wc2 = (const float*)d_in[8];
    const float* bc2 = (const float*)d_in[9];
    const float* Wn1 = (const float*)d_in[10];
    const float* bn1 = (const float*)d_in[11];
    const float* Wn2 = (const float*)d_in[12];
    const float* bn2 = (const float*)d_in[13];
    float* out = (float*)d_out;

    cudaFuncSetAttribute(pre_kernel,  cudaFuncAttributeMaxDynamicSharedMemorySize, PRE_SMEM_BYTES);
    cudaFuncSetAttribute(edge_kernel, cudaFuncAttributeMaxDynamicSharedMemorySize, EDGE_SMEM_BYTES);
    cudaFuncSetAttribute(node_kernel, cudaFuncAttributeMaxDynamicSharedMemorySize, NODE_SMEM_BYTES);

    detect_kernel<<<1, 32>>>((const int*)ei);
    zero_kernel<<<1024, 256>>>();
    pre_kernel<<<(NN + 63) / 64, 256, PRE_SMEM_BYTES>>>(x, We1);
    edge_kernel<<<(EE + 127) / 128, 256, EDGE_SMEM_BYTES>>>(
        x, ei, We1, be1, We2, be2, Wc1, bc1, Wc2, bc2);
    node_kernel<<<(NN + 63) / 64, 256, NODE_SMEM_BYTES>>>(
        x, Wn1, bn1, Wn2, bn2, out);
}

// round 9
// speedup vs baseline: 2.8270x; 1.0992x over previous
#include <cuda_runtime.h>
#include <cstdint>
#include <cstddef>

// Problem constants
#define NN 50000
#define EE 500000
// x row = 128 node feats + 3 coords = 131
// P table: row stride 1088 floats; P1 at col 0 (514 cols), P2 at col 544 (514 cols)
#define PSTRIDE 1088
#define P2OFF   544

__device__ float g_p[(size_t)NN * PSTRIDE]; // precomputed node @ [W_top | W_mid]
__device__ float g_m[NN * 64];   // segment-sum of m_ij
__device__ float g_w[NN];        // segment-sum of coord_w
__device__ float g_r[NN * 3];    // segment-sum of rel_coords
__device__ int   g_is64;         // edge_index dtype flag (1 = int64, 0 = int32)

__device__ __forceinline__ float silu_f(float v) {
    return __fdividef(v, 1.0f + __expf(-v));
}

// ---- packed fp32x2 helpers (Blackwell FFMA2) ------------------------------
typedef unsigned long long u64t;

__device__ __forceinline__ void ffma2(u64t& d, u64t a, u64t b) {
    asm("fma.rn.f32x2 %0, %1, %2, %3;" : "=l"(d) : "l"(a), "l"(b), "l"(d));
}
__device__ __forceinline__ u64t pack2s(float v) {   // (v, v)
    u64t r;
    unsigned int u = __float_as_uint(v);
    asm("mov.b64 %0, {%1, %2};" : "=l"(r) : "r"(u), "r"(u));
    return r;
}
__device__ __forceinline__ float2 unpack2(u64t v) {
    unsigned int lo, hi;
    asm("mov.b64 {%0, %1}, %2;" : "=r"(lo), "=r"(hi) : "l"(v));
    return make_float2(__uint_as_float(lo), __uint_as_float(hi));
}

// ---------------------------------------------------------------------------
__global__ void detect_kernel(const int* __restrict__ ei32) {
    if (threadIdx.x == 0 && blockIdx.x == 0) {
        int allzero = 1;
        #pragma unroll 1
        for (int i = 0; i < 64; i++) {
            if (ei32[2 * i + 1] != 0) { allzero = 0; break; }
        }
        g_is64 = allzero;
    }
}

__global__ void zero_kernel() {
    int stride = gridDim.x * blockDim.x;
    int i = blockIdx.x * blockDim.x + threadIdx.x;
    for (int k = i; k < NN * 64; k += stride) g_m[k] = 0.0f;
    for (int k = i; k < NN; k += stride) g_w[k] = 0.0f;
    for (int k = i; k < NN * 3; k += stride) g_r[k] = 0.0f;
}

// ---------------------------------------------------------------------------
// Precompute kernel: P[n, 0:514]   = node[n] @ We1[0:128, :]
//                    P[n, 544:1058]= node[n] @ We1[128:256, :]
// (writes zeros in gap cols, so downstream float4 reads are always valid)
// ---------------------------------------------------------------------------
#define PRE_SMEM_BYTES 66560

__global__ __launch_bounds__(256)
void pre_kernel(const float* __restrict__ x, const float* __restrict__ We1)
{
    extern __shared__ float sm[];
    float* s_x = sm;          // [64][132]
    float* s_w = sm + 8448;   // [128][64]

    const int tid  = threadIdx.x;
    const int lane = tid & 31;
    const int wrp  = tid >> 5;
    const int b0   = blockIdx.x * 64;

    for (int i = wrp; i < 64; i += 8) {
        int g = b0 + i;
        if (g < NN) {
            const float* xr = x + (size_t)g * 131;
            #pragma unroll
            for (int c = lane; c < 128; c += 32) s_x[i * 132 + c] = xr[c];
        } else {
            for (int c = lane; c < 128; c += 32) s_x[i * 132 + c] = 0.0f;
        }
    }
    __syncthreads();

    const int tx = tid & 15;   // 16 -> 4 cols each
    const int ty = tid >> 4;   // 16 -> 4 nodes each

    for (int chunk = 0; chunk < 17; chunk++) {
        int cw0 = chunk * 64;
        for (int idx = tid; idx < 8192; idx += 256) {
            int k = idx >> 6, j = idx & 63;
            int c = cw0 + j;
            float v = 0.0f;
            if (c < 514)                     v = We1[k * 514 + c];
            else if (c >= P2OFF && c < 1058) v = We1[(128 + k) * 514 + (c - P2OFF)];
            s_w[idx] = v;
        }
        __syncthreads();

        u64t accp[4][2];
        #pragma unroll
        for (int i = 0; i < 4; i++) { accp[i][0] = 0ull; accp[i][1] = 0ull; }

        for (int k = 0; k < 128; k += 4) {
            float4 a[4];
            #pragma unroll
            for (int i = 0; i < 4; i++)
                a[i] = *(const float4*)&s_x[(ty * 4 + i) * 132 + k];
            #pragma unroll
            for (int kk = 0; kk < 4; kk++) {
                ulonglong2 B = *(const ulonglong2*)&s_w[(k + kk) * 64 + (tx << 2)];
                #pragma unroll
                for (int i = 0; i < 4; i++) {
                    float av = (kk == 0) ? a[i].x : (kk == 1) ? a[i].y : (kk == 2) ? a[i].z : a[i].w;
                    u64t Ap = pack2s(av);
                    ffma2(accp[i][0], Ap, B.x);
                    ffma2(accp[i][1], Ap, B.y);
                }
            }
        }
        #pragma unroll
        for (int i = 0; i < 4; i++) {
            int g = b0 + ty * 4 + i;
            if (g < NN) {
                float2 v0 = unpack2(accp[i][0]);
                float2 v1 = unpack2(accp[i][1]);
                float4 v = make_float4(v0.x, v0.y, v1.x, v1.y);
                *(float4*)&g_p[(size_t)g * PSTRIDE + cw0 + (tx << 2)] = v;
            }
        }
        __syncthreads();
    }
}

// ---------------------------------------------------------------------------
// Edge kernel, software-pipelined:
//   per chunk: [silu+store h | stage We2] sync [prefetch next P + GEMM2] sync
// 128 edges/block, 256 threads; each thread-pair owns one edge's gather.
// Shared layout (floats):
//   s_h    [32][132]  off 0      (4224)
//   s_w2   [32][64]   off 4224   (2048)
//   s_m    [64][132]  off 6272   (8448)
//   s_wc   [64][32]   off 14720  (2048)
//   s_dst  int[128]   off 16768
//   s_soff int[128]   off 16896
//   s_dist [128]      off 17024
//   s_rel  [128*3]    off 17152
//   s_bb   [32]       off 17536
//   s_wd   [32]       off 17568
//   s_doff int[128]   off 17600
// total 17728 floats = 70912 bytes
// ---------------------------------------------------------------------------
#define EDGE_SMEM_BYTES 70912

__global__ __launch_bounds__(256, 2)
void edge_kernel(const float* __restrict__ x,
                 const void* __restrict__ ei_raw,
                 const float* __restrict__ We1, const float* __restrict__ be1,
                 const float* __restrict__ We2, const float* __restrict__ be2,
                 const float* __restrict__ Wc1, const float* __restrict__ bc1,
                 const float* __restrict__ Wc2, const float* __restrict__ bc2)
{
    extern __shared__ float sm[];
    float* s_h    = sm;                    // [32][132]
    float* s_w2   = sm + 4224;             // [32][64]
    float* s_m    = sm + 6272;             // [64][132]
    float* s_wc   = sm + 14720;            // [64][32]
    int*   s_dst  = (int*)(sm + 16768);
    int*   s_soff = (int*)(sm + 16896);
    float* s_dist = sm + 17024;
    float* s_rel  = sm + 17152;
    float* s_bb   = sm + 17536;
    float* s_wd   = sm + 17568;
    int*   s_doff = (int*)(sm + 17600);

    const int tid = threadIdx.x;
    const int is64 = g_is64;
    const long long* ei64 = (const long long*)ei_raw;
    const int*       ei32 = (const int*)ei_raw;

    // ---------------- edge meta + first bias/wd staging --------------------
    if (tid < 128) {
        int e = tid;
        long long ge = (long long)blockIdx.x * 128 + e;
        int s = -1, d = -1;
        if (ge < EE) {
            if (is64) { s = (int)ei64[ge]; d = (int)ei64[EE + ge]; }
            else      { s = ei32[ge];      d = ei32[EE + ge]; }
            if (s < 0 || s >= NN || d < 0 || d >= NN) { s = -1; d = -1; }
        }
        float r0 = 0.0f, r1 = 0.0f, r2 = 0.0f, dist = 0.0f;
        if (d >= 0) {
            const float* xs = x + (size_t)s * 131;
            const float* xd = x + (size_t)d * 131;
            r0 = xs[128] - xd[128];
            r1 = xs[129] - xd[129];
            r2 = xs[130] - xd[130];
            dist = sqrtf(r0 * r0 + r1 * r1 + r2 * r2);
        }
        s_dst[e]  = d;
        s_doff[e] = (d >= 0) ? d * PSTRIDE : 0;
        s_soff[e] = (d >= 0) ? s * PSTRIDE + P2OFF : P2OFF;
        s_dist[e] = dist;
        s_rel[e * 3 + 0] = r0;
        s_rel[e * 3 + 1] = r1;
        s_rel[e * 3 + 2] = r2;
    }
    if (tid < 32) {                       // chunk-0 bias + dist-row
        s_bb[tid] = be1[tid];
        s_wd[tid] = We1[256 * 514 + tid];
    }
    __syncthreads();

    const int e_g = tid >> 1;              // edge owned by this thread (pairwise)
    const int qb  = tid & 1;               // quad base: q = qb + 2*it
    const int dflag = s_dst[e_g];
    const int doff  = s_doff[e_g];
    const int soff  = s_soff[e_g];
    const float dist = s_dist[e_g];

    const int tx = tid & 15;               // 16 col/n threads
    const int ty = tid >> 4;               // 16 edge-groups of 8
    const int e0 = ty * 8;

    u64t macc[4][4];                       // edge-pair p x n-col j
    #pragma unroll
    for (int p = 0; p < 4; p++)
        #pragma unroll
        for (int j = 0; j < 4; j++) macc[p][j] = 0ull;

    // prefetch chunk 0 P values
    float4 P1[4], P2[4];
    #pragma unroll
    for (int it = 0; it < 4; it++) {
        int c = 4 * (qb + 2 * it);
        P1[it] = *(const float4*)&g_p[(size_t)(doff + c)];
        P2[it] = *(const float4*)&g_p[(size_t)(soff + c)];
    }
    float4 T1 = make_float4(0.f, 0.f, 0.f, 0.f);
    float4 T2 = make_float4(0.f, 0.f, 0.f, 0.f);

    // ---------------- 16 pipelined chunks (cols 0..511) --------------------
    for (int chunk = 0; chunk < 16; chunk++) {
        int c0 = chunk * 32;

        // phase A: silu + store s_h(chunk); stage s_w2(chunk)
        #pragma unroll
        for (int it = 0; it < 4; it++) {
            int q = qb + 2 * it;
            float4 wd4 = *(const float4*)&s_wd[4 * q];
            float4 bb4 = *(const float4*)&s_bb[4 * q];
            float h0 = silu_f(fmaf(dist, wd4.x, P1[it].x + P2[it].x + bb4.x));
            float h1 = silu_f(fmaf(dist, wd4.y, P1[it].y + P2[it].y + bb4.y));
            float h2 = silu_f(fmaf(dist, wd4.z, P1[it].z + P2[it].z + bb4.z));
            float h3 = silu_f(fmaf(dist, wd4.w, P1[it].w + P2[it].w + bb4.w));
            if (dflag < 0) { h0 = 0.f; h1 = 0.f; h2 = 0.f; h3 = 0.f; }
            s_h[(4 * q + 0) * 132 + e_g] = h0;
            s_h[(4 * q + 1) * 132 + e_g] = h1;
            s_h[(4 * q + 2) * 132 + e_g] = h2;
            s_h[(4 * q + 3) * 132 + e_g] = h3;
        }
        #pragma unroll
        for (int l = 0; l < 8; l++) {
            int idx = l * 256 + tid;
            int k = idx >> 6, j = idx & 63;
            s_w2[idx] = We2[(c0 + k) * 64 + j];      // c0+k <= 511 < 514
        }
        __syncthreads();

        // phase C: prefetch next chunk's P; stage next bb/wd; GEMM2(chunk)
        if (chunk < 15) {
            int c0n = c0 + 32;
            #pragma unroll
            for (int it = 0; it < 4; it++) {
                int c = c0n + 4 * (qb + 2 * it);
                P1[it] = *(const float4*)&g_p[(size_t)(doff + c)];
                P2[it] = *(const float4*)&g_p[(size_t)(soff + c)];
            }
            if (tid < 32) {
                int col = c0n + tid;                 // <= 511 < 514
                s_bb[tid] = be1[col];
                s_wd[tid] = We1[256 * 514 + col];
            }
        } else if (qb == 0) {
            // tail prefetch: cols 512..515 (use .x/.y only)
            T1 = *(const float4*)&g_p[(size_t)(doff + 512)];
            T2 = *(const float4*)&g_p[(size_t)(soff + 512)];
        }

        // GEMM2 (FFMA2): macc += h_chunk @ We2_chunk
        #pragma unroll 4
        for (int c = 0; c < 32; c++) {
            ulonglong2 A0 = *(const ulonglong2*)&s_h[c * 132 + e0];
            ulonglong2 A1 = *(const ulonglong2*)&s_h[c * 132 + e0 + 4];
            float4 bv = *(const float4*)&s_w2[c * 64 + (tx << 2)];
            u64t B0 = pack2s(bv.x), B1 = pack2s(bv.y), B2 = pack2s(bv.z), B3 = pack2s(bv.w);
            ffma2(macc[0][0], A0.x, B0); ffma2(macc[0][1], A0.x, B1);
            ffma2(macc[0][2], A0.x, B2); ffma2(macc[0][3], A0.x, B3);
            ffma2(macc[1][0], A0.y, B0); ffma2(macc[1][1], A0.y, B1);
            ffma2(macc[1][2], A0.y, B2); ffma2(macc[1][3], A0.y, B3);
            ffma2(macc[2][0], A1.x, B0); ffma2(macc[2][1], A1.x, B1);
            ffma2(macc[2][2], A1.x, B2); ffma2(macc[2][3], A1.x, B3);
            ffma2(macc[3][0], A1.y, B0); ffma2(macc[3][1], A1.y, B1);
            ffma2(macc[3][2], A1.y, B2); ffma2(macc[3][3], A1.y, B3);
        }
        __syncthreads();
    }

    // ---------------- tail: cols 512, 513 ----------------------------------
    if (tid < 128)
        s_w2[tid] = We2[(512 + (tid >> 6)) * 64 + (tid & 63)];
    if (qb == 0) {
        float wd0 = We1[256 * 514 + 512], wd1 = We1[256 * 514 + 513];
        float b0 = be1[512], b1 = be1[513];
        float h0 = silu_f(fmaf(dist, wd0, T1.x + T2.x + b0));
        float h1 = silu_f(fmaf(dist, wd1, T1.y + T2.y + b1));
        if (dflag < 0) { h0 = 0.f; h1 = 0.f; }
        s_h[e_g]       = h0;
        s_h[132 + e_g] = h1;
    }
    __syncthreads();
    #pragma unroll
    for (int c = 0; c < 2; c++) {
        ulonglong2 A0 = *(const ulonglong2*)&s_h[c * 132 + e0];
        ulonglong2 A1 = *(const ulonglong2*)&s_h[c * 132 + e0 + 4];
        float4 bv = *(const float4*)&s_w2[c * 64 + (tx << 2)];
        u64t B0 = pack2s(bv.x), B1 = pack2s(bv.y), B2 = pack2s(bv.z), B3 = pack2s(bv.w);
        ffma2(macc[0][0], A0.x, B0); ffma2(macc[0][1], A0.x, B1);
        ffma2(macc[0][2], A0.x, B2); ffma2(macc[0][3], A0.x, B3);
        ffma2(macc[1][0], A0.y, B0); ffma2(macc[1][1], A0.y, B1);
        ffma2(macc[1][2], A0.y, B2); ffma2(macc[1][3], A0.y, B3);
        ffma2(macc[2][0], A1.x, B0); ffma2(macc[2][1], A1.x, B1);
        ffma2(macc[2][2], A1.x, B2); ffma2(macc[2][3], A1.x, B3);
        ffma2(macc[3][0], A1.y, B0); ffma2(macc[3][1], A1.y, B1);
        ffma2(macc[3][2], A1.y, B2); ffma2(macc[3][3], A1.y, B3);
    }
    __syncthreads();

    // ---------------- m_ij = silu(m + b_e2); store + atomic scatter --------
    float mval[8][4];
    #pragma unroll
    for (int j = 0; j < 4; j++) {
        float b = be2[tx * 4 + j];
        #pragma unroll
        for (int p = 0; p < 4; p++) {
            float2 v = unpack2(macc[p][j]);
            mval[2 * p][j]     = silu_f(v.x + b);
            mval[2 * p + 1][j] = silu_f(v.y + b);
        }
    }
    #pragma unroll
    for (int j = 0; j < 4; j++)
        #pragma unroll
        for (int i = 0; i < 8; i++)
            s_m[(tx * 4 + j) * 132 + e0 + i] = mval[i][j];
    #pragma unroll
    for (int i = 0; i < 8; i++) {
        int d = s_dst[e0 + i];
        if (d >= 0) {
            #pragma unroll
            for (int j = 0; j < 4; j++)
                atomicAdd(&g_m[d * 64 + tx * 4 + j], mval[i][j]);
        }
    }
    __syncthreads();

    // ---------------- GEMM3 (64->256) + silu + dot W_c2 (FFMA2) ------------
    float cw[8];
    #pragma unroll
    for (int i = 0; i < 8; i++) cw[i] = 0.0f;

    for (int c0 = 0; c0 < 256; c0 += 32) {
        for (int idx = tid; idx < 2048; idx += 256) {
            int k = idx >> 5, j = idx & 31;
            s_wc[idx] = Wc1[k * 256 + c0 + j];
        }
        __syncthreads();

        u64t acc[4][2];
        #pragma unroll
        for (int p = 0; p < 4; p++) { acc[p][0] = 0ull; acc[p][1] = 0ull; }

        for (int k = 0; k < 64; k += 4) {
            #pragma unroll
            for (int kk = 0; kk < 4; kk++) {
                ulonglong2 A0 = *(const ulonglong2*)&s_m[(k + kk) * 132 + e0];
                ulonglong2 A1 = *(const ulonglong2*)&s_m[(k + kk) * 132 + e0 + 4];
                float2 bv = *(const float2*)&s_wc[(k + kk) * 32 + (tx << 1)];
                u64t B0 = pack2s(bv.x), B1 = pack2s(bv.y);
                ffma2(acc[0][0], A0.x, B0); ffma2(acc[0][1], A0.x, B1);
                ffma2(acc[1][0], A0.y, B0); ffma2(acc[1][1], A0.y, B1);
                ffma2(acc[2][0], A1.x, B0); ffma2(acc[2][1], A1.x, B1);
                ffma2(acc[3][0], A1.y, B0); ffma2(acc[3][1], A1.y, B1);
            }
        }
        float bb0 = bc1[c0 + tx * 2], bb1 = bc1[c0 + tx * 2 + 1];
        float w20 = Wc2[c0 + tx * 2], w21 = Wc2[c0 + tx * 2 + 1];
        #pragma unroll
        for (int p = 0; p < 4; p++) {
            float2 v0 = unpack2(acc[p][0]);
            float2 v1 = unpack2(acc[p][1]);
            cw[2 * p]     += silu_f(v0.x + bb0) * w20 + silu_f(v1.x + bb1) * w21;
            cw[2 * p + 1] += silu_f(v0.y + bb0) * w20 + silu_f(v1.y + bb1) * w21;
        }
        __syncthreads();
    }

    // reduce coord_w over 16 tx lanes (xor stays within 16-lane halves)
    #pragma unroll
    for (int off = 8; off >= 1; off >>= 1)
        #pragma unroll
        for (int i = 0; i < 8; i++)
            cw[i] += __shfl_xor_sync(0xffffffffu, cw[i], off);

    if (tx == 0) {
        float bc2v = bc2[0];
        #pragma unroll
        for (int i = 0; i < 8; i++) {
            int d = s_dst[e0 + i];
            if (d >= 0) {
                atomicAdd(&g_w[d], cw[i] + bc2v);
                atomicAdd(&g_r[d * 3 + 0], s_rel[(e0 + i) * 3 + 0]);
                atomicAdd(&g_r[d * 3 + 1], s_rel[(e0 + i) * 3 + 1]);
                atomicAdd(&g_r[d * 3 + 2], s_rel[(e0 + i) * 3 + 2]);
            }
        }
    }
}

// ---------------------------------------------------------------------------
// Node kernel: coords_out + fused MLP (192->256 silu ->128) + residual
// ---------------------------------------------------------------------------
#define NODE_SMEM_BYTES 99840

__global__ __launch_bounds__(256)
void node_kernel(const float* __restrict__ x,
                 const float* __restrict__ Wn1, const float* __restrict__ bn1,
                 const float* __restrict__ Wn2, const float* __restrict__ bn2,
                 float* __restrict__ out)
{
    extern __shared__ float sm[];
    float* s_nin = sm;              // [64][196]
    float* s_w1  = sm + 12544;      // [192][32]
    float* s_h1  = sm + 18688;      // [32][68]
    float* s_w2  = sm + 20864;      // [32][128]

    const int tid  = threadIdx.x;
    const int lane = tid & 31;
    const int wrp  = tid >> 5;
    const int b0   = blockIdx.x * 64;

    for (int i = wrp; i < 64; i += 8) {
        int g = b0 + i;
        if (g < NN) {
            const float* xr = x + (size_t)g * 131;
            #pragma unroll
            for (int c = lane; c < 128; c += 32) s_nin[i * 196 + c] = xr[c];
            #pragma unroll
            for (int c = lane; c < 64; c += 32) s_nin[i * 196 + 128 + c] = g_m[g * 64 + c];
            if (lane < 4) s_nin[i * 196 + 192 + lane] = 0.0f;
            if (lane < 3)
                out[(size_t)g * 131 + 128 + lane] = xr[128 + lane] + g_w[g] * g_r[g * 3 + lane];
        } else {
            for (int c = lane; c < 196; c += 32) s_nin[i * 196 + c] = 0.0f;
        }
    }
    __syncthreads();

    const int tx = tid & 15;
    const int ty = tid >> 4;

    u64t pacc[4][4];   // node i x col-pair q
    #pragma unroll
    for (int i = 0; i < 4; i++)
        #pragma unroll
        for (int q = 0; q < 4; q++) pacc[i][q] = 0ull;

    for (int c0 = 0; c0 < 256; c0 += 32) {
        for (int idx = tid; idx < 6144; idx += 256) {
            int k = idx >> 5, j = idx & 31;
            s_w1[idx] = Wn1[k * 256 + c0 + j];
        }
        __syncthreads();

        u64t acc1p[4];
        #pragma unroll
        for (int i = 0; i < 4; i++) acc1p[i] = 0ull;

        for (int k = 0; k < 192; k += 4) {
            float4 a[4];
            #pragma unroll
            for (int i = 0; i < 4; i++)
                a[i] = *(const float4*)&s_nin[(ty * 4 + i) * 196 + k];
            #pragma unroll
            for (int kk = 0; kk < 4; kk++) {
                u64t bp = *(const u64t*)&s_w1[(k + kk) * 32 + (tx << 1)];
                #pragma unroll
                for (int i = 0; i < 4; i++) {
                    float av = (kk == 0) ? a[i].x : (kk == 1) ? a[i].y : (kk == 2) ? a[i].z : a[i].w;
                    ffma2(acc1p[i], pack2s(av), bp);
                }
            }
        }
        __syncthreads();

        {
            float bjx = bn1[c0 + tx * 2];
            float bjy = bn1[c0 + tx * 2 + 1];
            #pragma unroll
            for (int i = 0; i < 4; i++) {
                float2 v = unpack2(acc1p[i]);
                s_h1[(tx * 2)     * 68 + ty * 4 + i] = silu_f(v.x + bjx);
                s_h1[(tx * 2 + 1) * 68 + ty * 4 + i] = silu_f(v.y + bjy);
            }
        }
        for (int idx = tid; idx < 4096; idx += 256) {
            int k = idx >> 7, j = idx & 127;
            s_w2[idx] = Wn2[(c0 + k) * 128 + j];
        }
        __syncthreads();

        #pragma unroll 4
        for (int c = 0; c < 32; c++) {
            float4 a = *(const float4*)&s_h1[c * 68 + ty * 4];
            ulonglong2 B0 = *(const ulonglong2*)&s_w2[c * 128 + tx * 8];
            ulonglong2 B1 = *(const ulonglong2*)&s_w2[c * 128 + tx * 8 + 4];
            #pragma unroll
            for (int i = 0; i < 4; i++) {
                float av = (i == 0) ? a.x : (i == 1) ? a.y : (i == 2) ? a.z : a.w;
                u64t Ap = pack2s(av);
                ffma2(pacc[i][0], Ap, B0.x);
                ffma2(pacc[i][1], Ap, B0.y);
                ffma2(pacc[i][2], Ap, B1.x);
                ffma2(pacc[i][3], Ap, B1.y);
            }
        }
        __syncthreads();
    }

    #pragma unroll
    for (int i = 0; i < 4; i++) {
        int g = b0 + ty * 4 + i;
        if (g < NN) {
            #pragma unroll
            for (int q = 0; q < 4; q++) {
                float2 v = unpack2(pacc[i][q]);
                int col = tx * 8 + 2 * q;
                out[(size_t)g * 131 + col] =
                    v.x + bn2[col] + s_nin[(ty * 4 + i) * 196 + col];
                out[(size_t)g * 131 + col + 1] =
                    v.y + bn2[col + 1] + s_nin[(ty * 4 + i) * 196 + col + 1];
            }
        }
    }
}

// ---------------------------------------------------------------------------
extern "C" void kernel_launch(void* const* d_in, const int* in_sizes, int n_in,
                              void* d_out, int out_size)
{
    const float* x   = (const float*)d_in[0];
    const void*  ei  = d_in[1];
    const float* We1 = (const float*)d_in[2];
    const float* be1 = (const float*)d_in[3];
    const float* We2 = (const float*)d_in[4];
    const float* be2 = (const float*)d_in[5];
    const float* Wc1 = (const float*)d_in[6];
    const float* bc1 = (const float*)d_in[7];
    const float* Wc2 = (const float*)d_in[8];
    const float* bc2 = (const float*)d_in[9];
    const float* Wn1 = (const float*)d_in[10];
    const float* bn1 = (const float*)d_in[11];
    const float* Wn2 = (const float*)d_in[12];
    const float* bn2 = (const float*)d_in[13];
    float* out = (float*)d_out;

    cudaFuncSetAttribute(pre_kernel,  cudaFuncAttributeMaxDynamicSharedMemorySize, PRE_SMEM_BYTES);
    cudaFuncSetAttribute(edge_kernel, cudaFuncAttributeMaxDynamicSharedMemorySize, EDGE_SMEM_BYTES);
    cudaFuncSetAttribute(node_kernel, cudaFuncAttributeMaxDynamicSharedMemorySize, NODE_SMEM_BYTES);

    detect_kernel<<<1, 32>>>((const int*)ei);
    zero_kernel<<<1024, 256>>>();
    pre_kernel<<<(NN + 63) / 64, 256, PRE_SMEM_BYTES>>>(x, We1);
    edge_kernel<<<(EE + 127) / 128, 256, EDGE_SMEM_BYTES>>>(
        x, ei, We1, be1, We2, be2, Wc1, bc1, Wc2, bc2);
    node_kernel<<<(NN + 63) / 64, 256, NODE_SMEM_BYTES>>>(
        x, Wn1, bn1, Wn2, bn2, out);
}